// round 6
// baseline (speedup 1.0000x reference)
#include <cuda_runtime.h>
#include <cuda_fp16.h>

// Problem constants (BOWRegressionMulti: T=200, B=1024, V=50000, L=512, PAD=1)
#define T_TOK 200
#define B_SZ  1024
#define V_SZ  50000
#define L_SZ  512
#define PAD_TOK 1
#define V_WORDS ((V_SZ + 31) / 32)

#define VTILES ((V_SZ + 63) / 64)          // 782
#define LTILES (L_SZ / 64)                 // 8
#define TR_BLOCKS (VTILES * LTILES)        // 6256 transpose blocks

// Scratch (static device globals — no allocs):
__device__ __half   g_Wt_h[(size_t)V_SZ * L_SZ];   // 51.2 MB transposed fp16 weights
__device__ unsigned g_toks[B_SZ][T_TOK];           // per-row deduped BYTE offsets (v*1024)
__device__ int      g_cnt[B_SZ];                   // per-row distinct-token counts

// ---------------------------------------------------------------------------
// K1 (fused): blocks [0, TR_BLOCKS) do the W[L,V] f32 -> Wt[V,L] f16 tiled
// transpose; blocks [TR_BLOCKS, TR_BLOCKS+B_SZ) do per-row token dedupe.
// Shared memory is one 16.6KB buffer reused by both roles.
// ---------------------------------------------------------------------------
__global__ __launch_bounds__(256) void bow_prep_kernel(
    const float* __restrict__ W,          // [L, V] f32
    const int*   __restrict__ text)       // [T, B] int32
{
    __shared__ float tile[64][65];        // 16.64 KB (transpose) / bitmap (dedupe)
    const int bid = blockIdx.x;
    const int tid = threadIdx.x;

    if (bid < TR_BLOCKS) {
        // ---------------- transpose role ----------------
        const int v0 = (bid % VTILES) * 64;
        const int l0 = (bid / VTILES) * 64;

        {
            const int tx = tid & 15;
            const int ty = tid >> 4;
            const int v  = v0 + tx * 4;
            #pragma unroll
            for (int p = 0; p < 4; p++) {
                const int l = ty + p * 16;
                float4 val = make_float4(0.f, 0.f, 0.f, 0.f);
                if (v < V_SZ) {
                    val = __ldcs((const float4*)(W + (size_t)(l0 + l) * V_SZ + v));
                }
                tile[l][tx * 4 + 0] = val.x;
                tile[l][tx * 4 + 1] = val.y;
                tile[l][tx * 4 + 2] = val.z;
                tile[l][tx * 4 + 3] = val.w;
            }
        }
        __syncthreads();

        {
            const int wx = tid & 7;
            const int wy = tid >> 3;
            #pragma unroll
            for (int p = 0; p < 2; p++) {
                const int vr = wy + p * 32;
                const int v  = v0 + vr;
                if (v < V_SZ) {
                    const int lbase = wx * 8;
                    __half2 h[4];
                    #pragma unroll
                    for (int k = 0; k < 4; k++) {
                        h[k] = __floats2half2_rn(tile[lbase + 2 * k][vr],
                                                 tile[lbase + 2 * k + 1][vr]);
                    }
                    uint4 pkt;
                    pkt.x = *(unsigned int*)&h[0];
                    pkt.y = *(unsigned int*)&h[1];
                    pkt.z = *(unsigned int*)&h[2];
                    pkt.w = *(unsigned int*)&h[3];
                    *(uint4*)(g_Wt_h + (size_t)v * L_SZ + l0 + lbase) = pkt;
                }
            }
        }
    } else {
        // ---------------- dedupe role ----------------
        const int b = bid - TR_BLOCKS;
        unsigned int* bitmap = (unsigned int*)&tile[0][0];   // V_WORDS = 1563 words
        __shared__ int cnt;

        for (int i = tid; i < V_WORDS; i += 256) bitmap[i] = 0u;
        if (tid == 0) cnt = 0;
        __syncthreads();

        if (tid < T_TOK) {
            int v = text[(size_t)tid * B_SZ + b];
            if (v != PAD_TOK && (unsigned)v < (unsigned)V_SZ) {
                unsigned int bit = 1u << (v & 31);
                unsigned int old = atomicOr(&bitmap[v >> 5], bit);
                if (!(old & bit)) {
                    int idx = atomicAdd(&cnt, 1);
                    g_toks[b][idx] = (unsigned)v * (L_SZ * 2);  // byte offset
                }
            }
        }
        __syncthreads();
        if (tid == 0) g_cnt[b] = cnt;
    }
}

// ---------------------------------------------------------------------------
// K2: gather. One block = one batch row, 256 threads; thread t owns labels
// [2t, 2t+1] (one 4B half2 load per token). 8 independent fp32 accumulators.
// Prologue is just a <=200-word offset copy (0.8KB smem).
// ---------------------------------------------------------------------------
__global__ __launch_bounds__(256) void bow_gather_kernel(
    const float* __restrict__ bias,       // [L]
    float* __restrict__ out)              // [B, L]
{
    __shared__ unsigned offs[T_TOK];
    const int b   = blockIdx.x;
    const int tid = threadIdx.x;

    const int n = g_cnt[b];
    if (tid < T_TOK && tid < n) offs[tid] = g_toks[b][tid];
    __syncthreads();

    const char* Wb = (const char*)g_Wt_h + (size_t)tid * 4;  // this thread's 2 labels

    float2 a0 = ((const float2*)bias)[tid];
    float2 a1 = make_float2(0.f, 0.f);
    float2 a2 = make_float2(0.f, 0.f);
    float2 a3 = make_float2(0.f, 0.f);
    float2 a4 = make_float2(0.f, 0.f);
    float2 a5 = make_float2(0.f, 0.f);
    float2 a6 = make_float2(0.f, 0.f);
    float2 a7 = make_float2(0.f, 0.f);

    int j = 0;
    for (; j + 8 <= n; j += 8) {
        unsigned int u0 = *(const unsigned int*)(Wb + offs[j + 0]);
        unsigned int u1 = *(const unsigned int*)(Wb + offs[j + 1]);
        unsigned int u2 = *(const unsigned int*)(Wb + offs[j + 2]);
        unsigned int u3 = *(const unsigned int*)(Wb + offs[j + 3]);
        unsigned int u4 = *(const unsigned int*)(Wb + offs[j + 4]);
        unsigned int u5 = *(const unsigned int*)(Wb + offs[j + 5]);
        unsigned int u6 = *(const unsigned int*)(Wb + offs[j + 6]);
        unsigned int u7 = *(const unsigned int*)(Wb + offs[j + 7]);
        float2 f;
        f = __half22float2(*(const __half2*)&u0); a0.x += f.x; a0.y += f.y;
        f = __half22float2(*(const __half2*)&u1); a1.x += f.x; a1.y += f.y;
        f = __half22float2(*(const __half2*)&u2); a2.x += f.x; a2.y += f.y;
        f = __half22float2(*(const __half2*)&u3); a3.x += f.x; a3.y += f.y;
        f = __half22float2(*(const __half2*)&u4); a4.x += f.x; a4.y += f.y;
        f = __half22float2(*(const __half2*)&u5); a5.x += f.x; a5.y += f.y;
        f = __half22float2(*(const __half2*)&u6); a6.x += f.x; a6.y += f.y;
        f = __half22float2(*(const __half2*)&u7); a7.x += f.x; a7.y += f.y;
    }
    for (; j < n; j++) {
        unsigned int u = *(const unsigned int*)(Wb + offs[j]);
        float2 f = __half22float2(*(const __half2*)&u);
        a0.x += f.x; a0.y += f.y;
    }

    float2 r;
    r.x = ((a0.x + a1.x) + (a2.x + a3.x)) + ((a4.x + a5.x) + (a6.x + a7.x));
    r.y = ((a0.y + a1.y) + (a2.y + a3.y)) + ((a4.y + a5.y) + (a6.y + a7.y));

    ((float2*)out)[(size_t)b * (L_SZ / 2) + tid] = r;
}

// ---------------------------------------------------------------------------
// Launch: fused prep (transpose + dedupe) then gather. Graph-capturable.
// Inputs: [0] text int32 [T,B], [1] W f32 [L,V], [2] b f32 [L].
// ---------------------------------------------------------------------------
extern "C" void kernel_launch(void* const* d_in, const int* in_sizes, int n_in,
                              void* d_out, int out_size) {
    const int*   text = (const int*)d_in[0];
    const float* W    = (const float*)d_in[1];
    const float* bias = (const float*)d_in[2];
    float*       out  = (float*)d_out;

    bow_prep_kernel<<<TR_BLOCKS + B_SZ, 256>>>(W, text);
    bow_gather_kernel<<<B_SZ, 256>>>(bias, out);
}

// round 7
// speedup vs baseline: 1.1230x; 1.1230x over previous
#include <cuda_runtime.h>
#include <cuda_fp16.h>

// Problem constants (BOWRegressionMulti: T=200, B=1024, V=50000, L=512, PAD=1)
#define T_TOK 200
#define B_SZ  1024
#define V_SZ  50000
#define L_SZ  512
#define PAD_TOK 1
#define V_WORDS ((V_SZ + 31) / 32)

#define VTILES ((V_SZ + 63) / 64)          // 782
#define LTILES (L_SZ / 64)                 // 8
#define TR_BLOCKS (VTILES * LTILES)        // 6256 transpose blocks

// Scratch (static device globals — no allocs):
__device__ __half   g_Wt_h[(size_t)V_SZ * L_SZ];   // 51.2 MB transposed fp16 weights
__device__ unsigned g_toks[B_SZ][T_TOK];           // per-row deduped WORD offsets (v*256)
__device__ int      g_cnt[B_SZ];                   // per-row distinct-token counts

// ---------------------------------------------------------------------------
// K1 (fused): blocks [0, TR_BLOCKS) do the W[L,V] f32 -> Wt[V,L] f16 tiled
// transpose; blocks [TR_BLOCKS, TR_BLOCKS+B_SZ) do per-row token dedupe.
// ---------------------------------------------------------------------------
__global__ __launch_bounds__(256) void bow_prep_kernel(
    const float* __restrict__ W,          // [L, V] f32
    const int*   __restrict__ text)       // [T, B] int32
{
    __shared__ float tile[64][65];        // 16.64 KB (transpose) / bitmap (dedupe)
    const int bid = blockIdx.x;
    const int tid = threadIdx.x;

    if (bid < TR_BLOCKS) {
        // ---------------- transpose role ----------------
        const int v0 = (bid % VTILES) * 64;
        const int l0 = (bid / VTILES) * 64;

        {
            const int tx = tid & 15;
            const int ty = tid >> 4;
            const int v  = v0 + tx * 4;
            #pragma unroll
            for (int p = 0; p < 4; p++) {
                const int l = ty + p * 16;
                float4 val = make_float4(0.f, 0.f, 0.f, 0.f);
                if (v < V_SZ) {
                    val = __ldcs((const float4*)(W + (size_t)(l0 + l) * V_SZ + v));
                }
                tile[l][tx * 4 + 0] = val.x;
                tile[l][tx * 4 + 1] = val.y;
                tile[l][tx * 4 + 2] = val.z;
                tile[l][tx * 4 + 3] = val.w;
            }
        }
        __syncthreads();

        {
            const int wx = tid & 7;
            const int wy = tid >> 3;
            #pragma unroll
            for (int p = 0; p < 2; p++) {
                const int vr = wy + p * 32;
                const int v  = v0 + vr;
                if (v < V_SZ) {
                    const int lbase = wx * 8;
                    __half2 h[4];
                    #pragma unroll
                    for (int k = 0; k < 4; k++) {
                        h[k] = __floats2half2_rn(tile[lbase + 2 * k][vr],
                                                 tile[lbase + 2 * k + 1][vr]);
                    }
                    uint4 pkt;
                    pkt.x = *(unsigned int*)&h[0];
                    pkt.y = *(unsigned int*)&h[1];
                    pkt.z = *(unsigned int*)&h[2];
                    pkt.w = *(unsigned int*)&h[3];
                    *(uint4*)(g_Wt_h + (size_t)v * L_SZ + l0 + lbase) = pkt;
                }
            }
        }
    } else {
        // ---------------- dedupe role ----------------
        const int b = bid - TR_BLOCKS;
        unsigned int* bitmap = (unsigned int*)&tile[0][0];   // V_WORDS = 1563 words
        __shared__ int cnt;

        for (int i = tid; i < V_WORDS; i += 256) bitmap[i] = 0u;
        if (tid == 0) cnt = 0;
        __syncthreads();

        if (tid < T_TOK) {
            int v = text[(size_t)tid * B_SZ + b];
            if (v != PAD_TOK && (unsigned)v < (unsigned)V_SZ) {
                unsigned int bit = 1u << (v & 31);
                unsigned int old = atomicOr(&bitmap[v >> 5], bit);
                if (!(old & bit)) {
                    int idx = atomicAdd(&cnt, 1);
                    g_toks[b][idx] = (unsigned)v * (L_SZ / 2);  // WORD offset (uint32 units)
                }
            }
        }
        __syncthreads();
        if (tid == 0) g_cnt[b] = cnt;
    }
}

// ---------------------------------------------------------------------------
// K2: gather. One block = one batch row, 256 threads; thread t owns labels
// [2t, 2t+1] (one 4B half2 load per token). 8 independent fp32 accumulators.
// __launch_bounds__(256, 8) pins regs <= 32 -> full occupancy (R6 lesson).
// ---------------------------------------------------------------------------
__global__ __launch_bounds__(256, 8) void bow_gather_kernel(
    const float* __restrict__ bias,       // [L]
    float* __restrict__ out)              // [B, L]
{
    __shared__ unsigned offs[T_TOK];
    const int b   = blockIdx.x;
    const int tid = threadIdx.x;

    const int n = g_cnt[b];
    if (tid < T_TOK) offs[tid] = g_toks[b][tid];
    __syncthreads();

    const unsigned int* Wu = (const unsigned int*)g_Wt_h;   // Wt as uint32 words

    float2 a0 = ((const float2*)bias)[tid];
    float2 a1 = make_float2(0.f, 0.f);
    float2 a2 = make_float2(0.f, 0.f);
    float2 a3 = make_float2(0.f, 0.f);
    float2 a4 = make_float2(0.f, 0.f);
    float2 a5 = make_float2(0.f, 0.f);
    float2 a6 = make_float2(0.f, 0.f);
    float2 a7 = make_float2(0.f, 0.f);

    int j = 0;
    for (; j + 8 <= n; j += 8) {
        unsigned int u0 = Wu[offs[j + 0] + tid];
        unsigned int u1 = Wu[offs[j + 1] + tid];
        unsigned int u2 = Wu[offs[j + 2] + tid];
        unsigned int u3 = Wu[offs[j + 3] + tid];
        unsigned int u4 = Wu[offs[j + 4] + tid];
        unsigned int u5 = Wu[offs[j + 5] + tid];
        unsigned int u6 = Wu[offs[j + 6] + tid];
        unsigned int u7 = Wu[offs[j + 7] + tid];
        float2 f;
        f = __half22float2(*(const __half2*)&u0); a0.x += f.x; a0.y += f.y;
        f = __half22float2(*(const __half2*)&u1); a1.x += f.x; a1.y += f.y;
        f = __half22float2(*(const __half2*)&u2); a2.x += f.x; a2.y += f.y;
        f = __half22float2(*(const __half2*)&u3); a3.x += f.x; a3.y += f.y;
        f = __half22float2(*(const __half2*)&u4); a4.x += f.x; a4.y += f.y;
        f = __half22float2(*(const __half2*)&u5); a5.x += f.x; a5.y += f.y;
        f = __half22float2(*(const __half2*)&u6); a6.x += f.x; a6.y += f.y;
        f = __half22float2(*(const __half2*)&u7); a7.x += f.x; a7.y += f.y;
    }
    for (; j < n; j++) {
        unsigned int u = Wu[offs[j] + tid];
        float2 f = __half22float2(*(const __half2*)&u);
        a0.x += f.x; a0.y += f.y;
    }

    float2 r;
    r.x = ((a0.x + a1.x) + (a2.x + a3.x)) + ((a4.x + a5.x) + (a6.x + a7.x));
    r.y = ((a0.y + a1.y) + (a2.y + a3.y)) + ((a4.y + a5.y) + (a6.y + a7.y));

    ((float2*)out)[(size_t)b * (L_SZ / 2) + tid] = r;
}

// ---------------------------------------------------------------------------
// Launch: fused prep (transpose + dedupe) then gather. Graph-capturable.
// Inputs: [0] text int32 [T,B], [1] W f32 [L,V], [2] b f32 [L].
// ---------------------------------------------------------------------------
extern "C" void kernel_launch(void* const* d_in, const int* in_sizes, int n_in,
                              void* d_out, int out_size) {
    const int*   text = (const int*)d_in[0];
    const float* W    = (const float*)d_in[1];
    const float* bias = (const float*)d_in[2];
    float*       out  = (float*)d_out;

    bow_prep_kernel<<<TR_BLOCKS + B_SZ, 256>>>(W, text);
    bow_gather_kernel<<<B_SZ, 256>>>(bias, out);
}

// round 8
// speedup vs baseline: 1.2500x; 1.1131x over previous
#include <cuda_runtime.h>
#include <cuda_fp16.h>

// Problem constants (BOWRegressionMulti: T=200, B=1024, V=50000, L=512, PAD=1)
#define T_TOK 200
#define B_SZ  1024
#define V_SZ  50000
#define L_SZ  512
#define PAD_TOK 1
#define V_WORDS ((V_SZ + 31) / 32)

#define VTILES ((V_SZ + 63) / 64)          // 782
#define LTILES (L_SZ / 64)                 // 8
#define TR_BLOCKS (VTILES * LTILES)        // 6256 transpose blocks

// Scratch (static device globals — no allocs):
__device__ __half   g_Wt_h[(size_t)V_SZ * L_SZ];   // 51.2 MB transposed fp16 weights
__device__ unsigned g_toks[B_SZ][T_TOK];           // per-row deduped WORD offsets (v*256)
__device__ int      g_cnt[B_SZ];                   // per-row distinct-token counts

// ---------------------------------------------------------------------------
// K1 (fused): blocks [0, TR_BLOCKS) do the W[L,V] f32 -> Wt[V,L] f16 tiled
// transpose; blocks [TR_BLOCKS, TR_BLOCKS+B_SZ) do per-row token dedupe.
// ---------------------------------------------------------------------------
__global__ __launch_bounds__(256) void bow_prep_kernel(
    const float* __restrict__ W,          // [L, V] f32
    const int*   __restrict__ text)       // [T, B] int32
{
    __shared__ float tile[64][65];        // 16.64 KB (transpose) / bitmap (dedupe)
    const int bid = blockIdx.x;
    const int tid = threadIdx.x;

    if (bid < TR_BLOCKS) {
        // ---------------- transpose role ----------------
        const int v0 = (bid % VTILES) * 64;
        const int l0 = (bid / VTILES) * 64;

        {
            const int tx = tid & 15;
            const int ty = tid >> 4;
            const int v  = v0 + tx * 4;
            #pragma unroll
            for (int p = 0; p < 4; p++) {
                const int l = ty + p * 16;
                float4 val = make_float4(0.f, 0.f, 0.f, 0.f);
                if (v < V_SZ) {
                    val = __ldcs((const float4*)(W + (size_t)(l0 + l) * V_SZ + v));
                }
                tile[l][tx * 4 + 0] = val.x;
                tile[l][tx * 4 + 1] = val.y;
                tile[l][tx * 4 + 2] = val.z;
                tile[l][tx * 4 + 3] = val.w;
            }
        }
        __syncthreads();

        {
            const int wx = tid & 7;
            const int wy = tid >> 3;
            #pragma unroll
            for (int p = 0; p < 2; p++) {
                const int vr = wy + p * 32;
                const int v  = v0 + vr;
                if (v < V_SZ) {
                    const int lbase = wx * 8;
                    __half2 h[4];
                    #pragma unroll
                    for (int k = 0; k < 4; k++) {
                        h[k] = __floats2half2_rn(tile[lbase + 2 * k][vr],
                                                 tile[lbase + 2 * k + 1][vr]);
                    }
                    uint4 pkt;
                    pkt.x = *(unsigned int*)&h[0];
                    pkt.y = *(unsigned int*)&h[1];
                    pkt.z = *(unsigned int*)&h[2];
                    pkt.w = *(unsigned int*)&h[3];
                    *(uint4*)(g_Wt_h + (size_t)v * L_SZ + l0 + lbase) = pkt;
                }
            }
        }
    } else {
        // ---------------- dedupe role ----------------
        const int b = bid - TR_BLOCKS;
        unsigned int* bitmap = (unsigned int*)&tile[0][0];   // V_WORDS = 1563 words
        __shared__ int cnt;

        for (int i = tid; i < V_WORDS; i += 256) bitmap[i] = 0u;
        if (tid == 0) cnt = 0;
        __syncthreads();

        if (tid < T_TOK) {
            int v = text[(size_t)tid * B_SZ + b];
            if (v != PAD_TOK && (unsigned)v < (unsigned)V_SZ) {
                unsigned int bit = 1u << (v & 31);
                unsigned int old = atomicOr(&bitmap[v >> 5], bit);
                if (!(old & bit)) {
                    int idx = atomicAdd(&cnt, 1);
                    g_toks[b][idx] = (unsigned)v * (L_SZ / 2);  // WORD offset (uint32 units)
                }
            }
        }
        __syncthreads();
        if (tid == 0) g_cnt[b] = cnt;
    }
}

// ---------------------------------------------------------------------------
// K2: gather. One block = one batch row, 256 threads; thread t owns labels
// [2t, 2t+1]. Pairwise fp16 pre-add (1 HADD2 per 2 tokens) before fp32
// accumulation cuts per-token issues ~40%; depth-1 tree keeps added rounding
// at ~= storage rounding. __launch_bounds__(256, 8) pins regs <= 32.
// ---------------------------------------------------------------------------
__global__ __launch_bounds__(256, 8) void bow_gather_kernel(
    const float* __restrict__ bias,       // [L]
    float* __restrict__ out)              // [B, L]
{
    __shared__ unsigned offs[T_TOK];
    const int b   = blockIdx.x;
    const int tid = threadIdx.x;

    const int n = g_cnt[b];
    if (tid < T_TOK) offs[tid] = g_toks[b][tid];
    __syncthreads();

    // Per-thread base: address = base + off*4 -> single IMAD.WIDE per load.
    const unsigned int* Wt_t = (const unsigned int*)g_Wt_h + tid;

    float2 a0 = ((const float2*)bias)[tid];
    float2 a1 = make_float2(0.f, 0.f);
    float2 a2 = make_float2(0.f, 0.f);
    float2 a3 = make_float2(0.f, 0.f);

    int j = 0;
    for (; j + 8 <= n; j += 8) {
        unsigned int u0 = Wt_t[offs[j + 0]];
        unsigned int u1 = Wt_t[offs[j + 1]];
        unsigned int u2 = Wt_t[offs[j + 2]];
        unsigned int u3 = Wt_t[offs[j + 3]];
        unsigned int u4 = Wt_t[offs[j + 4]];
        unsigned int u5 = Wt_t[offs[j + 5]];
        unsigned int u6 = Wt_t[offs[j + 6]];
        unsigned int u7 = Wt_t[offs[j + 7]];
        __half2 h0 = __hadd2(*(const __half2*)&u0, *(const __half2*)&u1);
        __half2 h1 = __hadd2(*(const __half2*)&u2, *(const __half2*)&u3);
        __half2 h2 = __hadd2(*(const __half2*)&u4, *(const __half2*)&u5);
        __half2 h3 = __hadd2(*(const __half2*)&u6, *(const __half2*)&u7);
        float2 f;
        f = __half22float2(h0); a0.x += f.x; a0.y += f.y;
        f = __half22float2(h1); a1.x += f.x; a1.y += f.y;
        f = __half22float2(h2); a2.x += f.x; a2.y += f.y;
        f = __half22float2(h3); a3.x += f.x; a3.y += f.y;
    }
    for (; j + 2 <= n; j += 2) {
        unsigned int u0 = Wt_t[offs[j + 0]];
        unsigned int u1 = Wt_t[offs[j + 1]];
        __half2 h = __hadd2(*(const __half2*)&u0, *(const __half2*)&u1);
        float2 f = __half22float2(h);
        a0.x += f.x; a0.y += f.y;
    }
    if (j < n) {
        unsigned int u = Wt_t[offs[j]];
        float2 f = __half22float2(*(const __half2*)&u);
        a1.x += f.x; a1.y += f.y;
    }

    float2 r;
    r.x = (a0.x + a1.x) + (a2.x + a3.x);
    r.y = (a0.y + a1.y) + (a2.y + a3.y);

    ((float2*)out)[(size_t)b * (L_SZ / 2) + tid] = r;
}

// ---------------------------------------------------------------------------
// Launch: fused prep (transpose + dedupe) then gather. Graph-capturable.
// Inputs: [0] text int32 [T,B], [1] W f32 [L,V], [2] b f32 [L].
// ---------------------------------------------------------------------------
extern "C" void kernel_launch(void* const* d_in, const int* in_sizes, int n_in,
                              void* d_out, int out_size) {
    const int*   text = (const int*)d_in[0];
    const float* W    = (const float*)d_in[1];
    const float* bias = (const float*)d_in[2];
    float*       out  = (float*)d_out;

    bow_prep_kernel<<<TR_BLOCKS + B_SZ, 256>>>(W, text);
    bow_gather_kernel<<<B_SZ, 256>>>(bias, out);
}